// round 3
// baseline (speedup 1.0000x reference)
#include <cuda_runtime.h>
#include <cuda_bf16.h>

// Problem: B=16, C=64, H=128, W=128.
// loss = sum_{b,c} [ sum_hw |pre-gt|*mask / max(count_nonzero(mask),1) ] / B
//
// Kernel 1: one CTA per (b,c) plane (1024 planes, 16384 floats each).
//           float4 loads of pre/gt/mask, manually unrolled x2 with loads
//           front-batched for MLP, block reduction, plane result ->
//           __device__ scratch (no atomics, deterministic).
// Kernel 2: single CTA reduces the 1024 plane values, divides by B.

#define NPLANES 1024
#define PLANE_ELEMS 16384           // 128*128
#define PLANE_VEC4 (PLANE_ELEMS/4)  // 4096
#define THREADS 256
#define BATCH 16.0f

__device__ float g_plane_loss[NPLANES];

__global__ __launch_bounds__(THREADS) void plane_kernel(
    const float* __restrict__ pre,
    const float* __restrict__ gt,
    const float* __restrict__ mask)
{
    const int plane = blockIdx.x;
    const size_t base = (size_t)plane * PLANE_ELEMS;
    const float4* __restrict__ p4 = (const float4*)(pre  + base);
    const float4* __restrict__ g4 = (const float4*)(gt   + base);
    const float4* __restrict__ m4 = (const float4*)(mask + base);

    float s = 0.0f;   // masked L1 sum
    float c = 0.0f;   // nonzero count

    // 4096 vec4 / 256 threads = 16 iters; unroll x2 -> 8 outer iters,
    // 6 independent LDG.128 front-batched per iter.
    for (int i = threadIdx.x; i < PLANE_VEC4; i += 2 * THREADS) {
        float4 a0 = p4[i];
        float4 b0 = g4[i];
        float4 m0 = m4[i];
        float4 a1 = p4[i + THREADS];
        float4 b1 = g4[i + THREADS];
        float4 m1 = m4[i + THREADS];

        s += fabsf(a0.x - b0.x) * m0.x;
        s += fabsf(a0.y - b0.y) * m0.y;
        s += fabsf(a0.z - b0.z) * m0.z;
        s += fabsf(a0.w - b0.w) * m0.w;
        c += (m0.x != 0.0f) ? 1.0f : 0.0f;
        c += (m0.y != 0.0f) ? 1.0f : 0.0f;
        c += (m0.z != 0.0f) ? 1.0f : 0.0f;
        c += (m0.w != 0.0f) ? 1.0f : 0.0f;

        s += fabsf(a1.x - b1.x) * m1.x;
        s += fabsf(a1.y - b1.y) * m1.y;
        s += fabsf(a1.z - b1.z) * m1.z;
        s += fabsf(a1.w - b1.w) * m1.w;
        c += (m1.x != 0.0f) ? 1.0f : 0.0f;
        c += (m1.y != 0.0f) ? 1.0f : 0.0f;
        c += (m1.z != 0.0f) ? 1.0f : 0.0f;
        c += (m1.w != 0.0f) ? 1.0f : 0.0f;
    }

    // warp reduce
    #pragma unroll
    for (int off = 16; off > 0; off >>= 1) {
        s += __shfl_xor_sync(0xFFFFFFFFu, s, off);
        c += __shfl_xor_sync(0xFFFFFFFFu, c, off);
    }

    __shared__ float ss[THREADS / 32];
    __shared__ float sc[THREADS / 32];
    const int wid = threadIdx.x >> 5;
    const int lid = threadIdx.x & 31;
    if (lid == 0) { ss[wid] = s; sc[wid] = c; }
    __syncthreads();

    if (wid == 0) {
        s = (lid < THREADS / 32) ? ss[lid] : 0.0f;
        c = (lid < THREADS / 32) ? sc[lid] : 0.0f;
        #pragma unroll
        for (int off = 4; off > 0; off >>= 1) {
            s += __shfl_xor_sync(0xFFFFFFFFu, s, off);
            c += __shfl_xor_sync(0xFFFFFFFFu, c, off);
        }
        if (lid == 0)
            g_plane_loss[plane] = s / fmaxf(c, 1.0f);
    }
}

__global__ __launch_bounds__(THREADS) void final_reduce_kernel(float* __restrict__ out)
{
    float s = 0.0f;
    #pragma unroll
    for (int i = threadIdx.x; i < NPLANES; i += THREADS)
        s += g_plane_loss[i];

    #pragma unroll
    for (int off = 16; off > 0; off >>= 1)
        s += __shfl_xor_sync(0xFFFFFFFFu, s, off);

    __shared__ float ss[THREADS / 32];
    const int wid = threadIdx.x >> 5;
    const int lid = threadIdx.x & 31;
    if (lid == 0) ss[wid] = s;
    __syncthreads();

    if (wid == 0) {
        s = (lid < THREADS / 32) ? ss[lid] : 0.0f;
        #pragma unroll
        for (int off = 4; off > 0; off >>= 1)
            s += __shfl_xor_sync(0xFFFFFFFFu, s, off);
        if (lid == 0)
            out[0] = s / BATCH;
    }
}

extern "C" void kernel_launch(void* const* d_in, const int* in_sizes, int n_in,
                              void* d_out, int out_size)
{
    const float* pre  = (const float*)d_in[0];
    const float* gt   = (const float*)d_in[1];
    const float* mask = (const float*)d_in[2];
    float* out = (float*)d_out;

    plane_kernel<<<NPLANES, THREADS>>>(pre, gt, mask);
    final_reduce_kernel<<<1, THREADS>>>(out);
}